// round 8
// baseline (speedup 1.0000x reference)
#include <cuda_runtime.h>
#include <cuda_fp16.h>
#include <math.h>
#include <stdint.h>

// ---------------- problem constants ----------------
#define E_ 8
#define B_ 2
#define N_ 2048
#define D_ 1024
#define F_ 4096
#define MTOT (E_*B_*N_)   // 32768 flat rows
#define RPE  (B_*N_)      // 4096 rows per expert

// ---------------- static scratch (allocation-free rule) ----------------
__device__ __half g_xh [(size_t)MTOT * D_];    //  64 MB : X fp16
__device__ __half g_w1h[(size_t)E_ * D_ * F_]; //  64 MB : W1 fp16 [E][D][F]
__device__ __half g_w2h[(size_t)E_ * F_ * D_]; //  64 MB : W2 fp16 [E][F][D]
__device__ __half g_hh [(size_t)MTOT * F_];    // 256 MB : H fp16

// ---------------- tiling ----------------
// A stage: 128 rows x 128 B (BK=64 halves), XOR-swizzled 16B chunks
// B stage: 64 rows x 256 B (BN=128 halves), XOR-swizzled 16B chunks
constexpr int BM = 128, BN = 128, BK = 64;
constexpr int ASTAGE_B = BM * 128;             // 16384 B
constexpr int BSTAGE_B = BK * 256;             // 16384 B
constexpr int STAGE_B  = ASTAGE_B + BSTAGE_B;  // 32768 B
constexpr size_t SMEM_BYTES = 2 * (size_t)STAGE_B; // 65536 B (double buffer)

// ---------------- helpers ----------------
__device__ __forceinline__ uint32_t s2u(const void* p) {
    uint32_t a;
    asm("{ .reg .u64 t; cvta.to.shared.u64 t, %1; cvt.u32.u64 %0, t; }" : "=r"(a) : "l"(p));
    return a;
}
__device__ __forceinline__ void cpa16(uint32_t s, const void* g) {
    asm volatile("cp.async.cg.shared.global [%0], [%1], 16;" :: "r"(s), "l"(g));
}
__device__ __forceinline__ void commitg() {
    asm volatile("cp.async.commit_group;" ::: "memory");
}
__device__ __forceinline__ void ldsm_x4(uint32_t* r, uint32_t a) {
    asm volatile("ldmatrix.sync.aligned.m8n8.x4.shared.b16 {%0,%1,%2,%3}, [%4];"
                 : "=r"(r[0]), "=r"(r[1]), "=r"(r[2]), "=r"(r[3]) : "r"(a));
}
__device__ __forceinline__ void ldsm_x4_t(uint32_t* r, uint32_t a) {
    asm volatile("ldmatrix.sync.aligned.m8n8.x4.trans.shared.b16 {%0,%1,%2,%3}, [%4];"
                 : "=r"(r[0]), "=r"(r[1]), "=r"(r[2]), "=r"(r[3]) : "r"(a));
}
__device__ __forceinline__ void mma_f16(float* c, const uint32_t* a, const uint32_t* b) {
    asm volatile(
        "mma.sync.aligned.m16n8k16.row.col.f32.f16.f16.f32 "
        "{%0,%1,%2,%3},{%4,%5,%6,%7},{%8,%9},{%0,%1,%2,%3};"
        : "+f"(c[0]), "+f"(c[1]), "+f"(c[2]), "+f"(c[3])
        : "r"(a[0]), "r"(a[1]), "r"(a[2]), "r"(a[3]), "r"(b[0]), "r"(b[1]));
}

// jax.nn.gelu default: approximate=True (tanh form)
__device__ __forceinline__ float gelu_tanh(float x) {
    float u = 0.7978845608028654f * fmaf(0.044715f * x, x * x, x);
    return 0.5f * x * (1.0f + tanhf(u));
}

// ---------------- stage loader (256 threads) ----------------
__device__ __forceinline__ void load_stage(uint32_t sbase, const __half* Ae, const __half* Be,
                                           int K, int Ncols, int kt, int tid) {
    const uint32_t ab = sbase + (kt & 1) * STAGE_B;
    const uint32_t bb = ab + ASTAGE_B;
    const char* ag = (const char*)(Ae + (size_t)kt * BK);
    const char* bg = (const char*)(Be + (size_t)kt * BK * Ncols);
    // A: 128 rows x 8 chunks = 1024 chunks ; 4 per thread
#pragma unroll
    for (int i = 0; i < 4; i++) {
        int c = tid + i * 256;
        int r = c >> 3, cb = c & 7;
        cpa16(ab + r * 128 + ((cb ^ (r & 7)) << 4), ag + (size_t)r * K * 2 + cb * 16);
    }
    // B: 64 rows x 16 chunks = 1024 chunks ; 4 per thread
#pragma unroll
    for (int i = 0; i < 4; i++) {
        int c = tid + i * 256;
        int r = c >> 4, cb = c & 15;
        cpa16(bb + r * 256 + ((cb ^ (r & 7)) << 4), bg + (size_t)r * Ncols * 2 + cb * 16);
    }
    commitg();
}

// ---------------- GEMM: C = act(A @ W_e + bias_e) ----------------
// A:[MTOT,K] fp16 rm; W:[E][K][Ncols] fp16 rm; bias:[E][Ncols] fp32
// block = 256 threads = 8 warps, warp tile 32x64 (4 warps along M, 2 along N)
template <bool GELU, bool OUTH>
__global__ void __launch_bounds__(256, 2)
gemm_hmma(const __half* __restrict__ A, const __half* __restrict__ W,
          const float* __restrict__ bias, void* __restrict__ Cv, int K, int Ncols)
{
    extern __shared__ char smem[];
    const uint32_t sb = s2u(smem);
    const int tid = threadIdx.x;
    const int warp = tid >> 5, lane = tid & 31;
    const int bm = blockIdx.y, bn = blockIdx.x;
    const int expert = (bm * BM) / RPE;

    const __half* Ae = A + (size_t)bm * BM * K;
    const __half* Be = W + (size_t)expert * K * Ncols + (size_t)bn * BN;

    const int wm = (warp & 3) * 32;   // 4 warps along M
    const int wn = (warp >> 2) * 64;  // 2 warps along N

    float acc[2][8][4];
#pragma unroll
    for (int mi = 0; mi < 2; mi++)
#pragma unroll
        for (int ni = 0; ni < 8; ni++)
#pragma unroll
            for (int r = 0; r < 4; r++) acc[mi][ni][r] = 0.0f;

    const int KT = K / BK;
    const int l16 = lane & 15, lh = lane >> 4;
    const int rxor = l16 & 7;         // row&7 == l16&7 for all fragment rows

    // hoisted swizzled offsets
    uint32_t a_row_b[2];
#pragma unroll
    for (int mi = 0; mi < 2; mi++)
        a_row_b[mi] = (wm + mi * 16 + l16) * 128;
    uint32_t a_chk[4];
#pragma unroll
    for (int ks = 0; ks < 4; ks++)
        a_chk[ks] = (uint32_t)(((ks * 2 + lh) ^ rxor) << 4);
    const uint32_t b_row_b = l16 * 256;
    uint32_t b_chk[4];
#pragma unroll
    for (int ni2 = 0; ni2 < 4; ni2++)
        b_chk[ni2] = (uint32_t)((((wn >> 3) + ni2 * 2 + lh) ^ rxor) << 4);

    load_stage(sb, Ae, Be, K, Ncols, 0, tid);

    for (int kt = 0; kt < KT; kt++) {
        asm volatile("cp.async.wait_group 0;" ::: "memory");
        __syncthreads();

        if (kt + 1 < KT) load_stage(sb, Ae, Be, K, Ncols, kt + 1, tid);

        const uint32_t ab = sb + (kt & 1) * STAGE_B;
        const uint32_t bb = ab + ASTAGE_B;

#pragma unroll
        for (int ks = 0; ks < 4; ks++) {
            uint32_t bf[8][2];
            const uint32_t bks = bb + b_row_b + ks * 16 * 256;
#pragma unroll
            for (int ni2 = 0; ni2 < 4; ni2++) {
                uint32_t t[4];
                ldsm_x4_t(t, bks + b_chk[ni2]);
                bf[ni2 * 2][0] = t[0]; bf[ni2 * 2][1] = t[1];
                bf[ni2 * 2 + 1][0] = t[2]; bf[ni2 * 2 + 1][1] = t[3];
            }
            uint32_t af[2][4];
#pragma unroll
            for (int mi = 0; mi < 2; mi++)
                ldsm_x4(af[mi], ab + a_row_b[mi] + a_chk[ks]);
#pragma unroll
            for (int mi = 0; mi < 2; mi++)
#pragma unroll
                for (int ni = 0; ni < 8; ni++)
                    mma_f16(acc[mi][ni], af[mi], bf[ni]);
        }
    }

    // epilogue: bias + optional gelu
    const int g = lane >> 2, t = lane & 3;
    const float* be = bias + (size_t)expert * Ncols + (size_t)bn * BN;

#pragma unroll
    for (int mi = 0; mi < 2; mi++) {
        const int gr0 = bm * BM + wm + mi * 16 + g;
#pragma unroll
        for (int ni = 0; ni < 8; ni++) {
            const int lc = wn + ni * 8 + 2 * t;
            const float bv0 = be[lc];
            const float bv1 = be[lc + 1];
            float v0 = acc[mi][ni][0] + bv0;
            float v1 = acc[mi][ni][1] + bv1;
            float v2 = acc[mi][ni][2] + bv0;
            float v3 = acc[mi][ni][3] + bv1;
            if (GELU) {
                v0 = gelu_tanh(v0); v1 = gelu_tanh(v1);
                v2 = gelu_tanh(v2); v3 = gelu_tanh(v3);
            }
            const size_t base0 = (size_t)gr0 * Ncols + (size_t)bn * BN + lc;
            const size_t base1 = (size_t)(gr0 + 8) * Ncols + (size_t)bn * BN + lc;
            if (OUTH) {
                __half* C = (__half*)Cv;
                *reinterpret_cast<__half2*>(C + base0) = __floats2half2_rn(v0, v1);
                *reinterpret_cast<__half2*>(C + base1) = __floats2half2_rn(v2, v3);
            } else {
                float* C = (float*)Cv;
                *reinterpret_cast<float2*>(C + base0) = make_float2(v0, v1);
                *reinterpret_cast<float2*>(C + base1) = make_float2(v2, v3);
            }
        }
    }
}

// ---------------- prepass: fp32 -> fp16 elementwise ----------------
__global__ void conv_h(const float* __restrict__ in, __half* __restrict__ out) {
    size_t i = ((size_t)blockIdx.x * blockDim.x + threadIdx.x) * 8;
    float4 v0 = *reinterpret_cast<const float4*>(in + i);
    float4 v1 = *reinterpret_cast<const float4*>(in + i + 4);
    __half2* o = reinterpret_cast<__half2*>(out + i);
    o[0] = __floats2half2_rn(v0.x, v0.y);
    o[1] = __floats2half2_rn(v0.z, v0.w);
    o[2] = __floats2half2_rn(v1.x, v1.y);
    o[3] = __floats2half2_rn(v1.z, v1.w);
}

// ---------------- launch ----------------
extern "C" void kernel_launch(void* const* d_in, const int* in_sizes, int n_in,
                              void* d_out, int out_size)
{
    const float* x  = (const float*)d_in[0];
    const float* w1 = (const float*)d_in[1];
    const float* b1 = (const float*)d_in[2];
    const float* w2 = (const float*)d_in[3];
    const float* b2 = (const float*)d_in[4];
    float* out = (float*)d_out;

    void *xh_p, *w1h_p, *w2h_p, *hh_p;
    cudaGetSymbolAddress(&xh_p,  g_xh);
    cudaGetSymbolAddress(&w1h_p, g_w1h);
    cudaGetSymbolAddress(&w2h_p, g_w2h);
    cudaGetSymbolAddress(&hh_p,  g_hh);
    __half* xh  = (__half*)xh_p;
    __half* w1h = (__half*)w1h_p;
    __half* w2h = (__half*)w2h_p;
    __half* hh  = (__half*)hh_p;

    cudaFuncSetAttribute(gemm_hmma<true, true>,
                         cudaFuncAttributeMaxDynamicSharedMemorySize, (int)SMEM_BYTES);
    cudaFuncSetAttribute(gemm_hmma<false, false>,
                         cudaFuncAttributeMaxDynamicSharedMemorySize, (int)SMEM_BYTES);

    // prepass conversions
    conv_h<<<(size_t)MTOT * D_ / (256 * 8), 256>>>(x, xh);
    conv_h<<<(size_t)E_ * D_ * F_ / (256 * 8), 256>>>(w1, w1h);
    conv_h<<<(size_t)E_ * F_ * D_ / (256 * 8), 256>>>(w2, w2h);

    // GEMM1: H = gelu(X @ W1 + b1)   M=32768, K=1024, N=4096 (fp16 out)
    gemm_hmma<true, true><<<dim3(F_ / BN, MTOT / BM), 256, SMEM_BYTES>>>(
        xh, w1h, b1, (void*)hh, D_, F_);
    // GEMM2: OUT = H @ W2 + b2       M=32768, K=4096, N=1024 (fp32 out)
    gemm_hmma<false, false><<<dim3(D_ / BN, MTOT / BM), 256, SMEM_BYTES>>>(
        hh, w2h, b2, (void*)out, F_, D_);
}

// round 9
// speedup vs baseline: 1.0910x; 1.0910x over previous
#include <cuda_runtime.h>
#include <cuda_fp16.h>
#include <math.h>
#include <stdint.h>

// ---------------- problem constants ----------------
#define E_ 8
#define B_ 2
#define N_ 2048
#define D_ 1024
#define F_ 4096
#define MTOT (E_*B_*N_)   // 32768 flat rows
#define RPE  (B_*N_)      // 4096 rows per expert

// ---------------- static scratch (allocation-free rule) ----------------
__device__ __half g_xh [(size_t)MTOT * D_];    //  64 MB : X fp16
__device__ __half g_w1h[(size_t)E_ * D_ * F_]; //  64 MB : W1 fp16 [E][D][F]
__device__ __half g_w2h[(size_t)E_ * F_ * D_]; //  64 MB : W2 fp16 [E][F][D]
__device__ __half g_hh [(size_t)MTOT * F_];    // 256 MB : H fp16

// ---------------- tiling ----------------
// A stage: 128 rows x 128 B (BK=64 halves), XOR-swizzled 16B chunks
// B stage: 64 rows x 256 B (BN=128 halves), XOR-swizzled 16B chunks
constexpr int BM = 128, BN = 128, BK = 64;
constexpr int ASTAGE_B = BM * 128;             // 16384 B
constexpr int BSTAGE_B = BK * 256;             // 16384 B
constexpr int STAGE_B  = ASTAGE_B + BSTAGE_B;  // 32768 B
constexpr size_t SMEM_BYTES = 2 * (size_t)STAGE_B; // 65536 B (double buffer)

// ---------------- helpers ----------------
__device__ __forceinline__ uint32_t s2u(const void* p) {
    uint32_t a;
    asm("{ .reg .u64 t; cvta.to.shared.u64 t, %1; cvt.u32.u64 %0, t; }" : "=r"(a) : "l"(p));
    return a;
}
__device__ __forceinline__ void cpa16(uint32_t s, const void* g) {
    asm volatile("cp.async.cg.shared.global [%0], [%1], 16;" :: "r"(s), "l"(g));
}
__device__ __forceinline__ void commitg() {
    asm volatile("cp.async.commit_group;" ::: "memory");
}
__device__ __forceinline__ void ldsm_x4(uint32_t* r, uint32_t a) {
    asm volatile("ldmatrix.sync.aligned.m8n8.x4.shared.b16 {%0,%1,%2,%3}, [%4];"
                 : "=r"(r[0]), "=r"(r[1]), "=r"(r[2]), "=r"(r[3]) : "r"(a));
}
__device__ __forceinline__ void ldsm_x4_t(uint32_t* r, uint32_t a) {
    asm volatile("ldmatrix.sync.aligned.m8n8.x4.trans.shared.b16 {%0,%1,%2,%3}, [%4];"
                 : "=r"(r[0]), "=r"(r[1]), "=r"(r[2]), "=r"(r[3]) : "r"(a));
}
__device__ __forceinline__ void mma_f16(float* c, const uint32_t* a, const uint32_t* b) {
    asm volatile(
        "mma.sync.aligned.m16n8k16.row.col.f32.f16.f16.f32 "
        "{%0,%1,%2,%3},{%4,%5,%6,%7},{%8,%9},{%0,%1,%2,%3};"
        : "+f"(c[0]), "+f"(c[1]), "+f"(c[2]), "+f"(c[3])
        : "r"(a[0]), "r"(a[1]), "r"(a[2]), "r"(a[3]), "r"(b[0]), "r"(b[1]));
}

// jax.nn.gelu default: approximate=True (tanh form)
__device__ __forceinline__ float gelu_tanh(float x) {
    float u = 0.7978845608028654f * fmaf(0.044715f * x, x * x, x);
    return 0.5f * x * (1.0f + tanhf(u));
}

// ---------------- stage loader (128 threads) ----------------
__device__ __forceinline__ void load_stage(uint32_t sbase, const __half* Ae, const __half* Be,
                                           int K, int Ncols, int kt, int tid) {
    const uint32_t ab = sbase + (kt & 1) * STAGE_B;
    const uint32_t bb = ab + ASTAGE_B;
    const char* ag = (const char*)(Ae + (size_t)kt * BK);
    const char* bg = (const char*)(Be + (size_t)kt * BK * Ncols);
    // A: 128 rows x 8 chunks = 1024 chunks ; 8 per thread
#pragma unroll
    for (int i = 0; i < 8; i++) {
        int c = tid + i * 128;
        int r = c >> 3, cb = c & 7;
        cpa16(ab + r * 128 + ((cb ^ (r & 7)) << 4), ag + (size_t)r * K * 2 + cb * 16);
    }
    // B: 64 rows x 16 chunks = 1024 chunks ; 8 per thread
#pragma unroll
    for (int i = 0; i < 8; i++) {
        int c = tid + i * 128;
        int r = c >> 4, cb = c & 15;
        cpa16(bb + r * 256 + ((cb ^ (r & 7)) << 4), bg + (size_t)r * Ncols * 2 + cb * 16);
    }
    commitg();
}

// ---------------- GEMM: C = act(A @ W_e + bias_e) ----------------
// A:[MTOT,K] fp16 rm; W:[E][K][Ncols] fp16 rm; bias:[E][Ncols] fp32
// block = 128 threads = 4 warps, warp tile 64x64
template <bool GELU, bool OUTH>
__global__ void __launch_bounds__(128, 2)
gemm_hmma(const __half* __restrict__ A, const __half* __restrict__ W,
          const float* __restrict__ bias, void* __restrict__ Cv, int K, int Ncols)
{
    extern __shared__ char smem[];
    const uint32_t sb = s2u(smem);
    const int tid = threadIdx.x;
    const int warp = tid >> 5, lane = tid & 31;
    const int bm = blockIdx.y, bn = blockIdx.x;
    const int expert = (bm * BM) / RPE;

    const __half* Ae = A + (size_t)bm * BM * K;
    const __half* Be = W + (size_t)expert * K * Ncols + (size_t)bn * BN;

    const int wm = (warp & 1) * 64;   // 2 warps along M
    const int wn = (warp >> 1) * 64;  // 2 warps along N

    float acc[4][8][4];
#pragma unroll
    for (int mi = 0; mi < 4; mi++)
#pragma unroll
        for (int ni = 0; ni < 8; ni++)
#pragma unroll
            for (int r = 0; r < 4; r++) acc[mi][ni][r] = 0.0f;

    const int KT = K / BK;
    const int l16 = lane & 15, lh = lane >> 4;
    const int rxor = l16 & 7;         // row&7 == l16&7 for all fragment rows

    // hoisted swizzled offsets
    uint32_t a_row_b[4];
#pragma unroll
    for (int mi = 0; mi < 4; mi++)
        a_row_b[mi] = (wm + mi * 16 + l16) * 128;
    uint32_t a_chk[4];
#pragma unroll
    for (int ks = 0; ks < 4; ks++)
        a_chk[ks] = (uint32_t)(((ks * 2 + lh) ^ rxor) << 4);
    const uint32_t b_row_b = l16 * 256;
    uint32_t b_chk[4];
#pragma unroll
    for (int ni2 = 0; ni2 < 4; ni2++)
        b_chk[ni2] = (uint32_t)((((wn >> 3) + ni2 * 2 + lh) ^ rxor) << 4);

    load_stage(sb, Ae, Be, K, Ncols, 0, tid);

    // register fragment double buffers
    uint32_t af[2][4][4];
    uint32_t bf[2][8][2];

    for (int kt = 0; kt < KT; kt++) {
        asm volatile("cp.async.wait_group 0;" ::: "memory");
        __syncthreads();

        if (kt + 1 < KT) load_stage(sb, Ae, Be, K, Ncols, kt + 1, tid);

        const uint32_t ab = sb + (kt & 1) * STAGE_B;
        const uint32_t bb = ab + ASTAGE_B;

        // prefetch fragments for ks = 0 into buffer 0
        {
            const uint32_t bks = bb + b_row_b;
#pragma unroll
            for (int ni2 = 0; ni2 < 4; ni2++) {
                uint32_t t[4];
                ldsm_x4_t(t, bks + b_chk[ni2]);
                bf[0][ni2 * 2][0] = t[0]; bf[0][ni2 * 2][1] = t[1];
                bf[0][ni2 * 2 + 1][0] = t[2]; bf[0][ni2 * 2 + 1][1] = t[3];
            }
#pragma unroll
            for (int mi = 0; mi < 4; mi++)
                ldsm_x4(af[0][mi], ab + a_row_b[mi] + a_chk[0]);
        }

#pragma unroll
        for (int ks = 0; ks < 4; ks++) {
            const int cur = ks & 1, nxt = cur ^ 1;
            // prefetch ks+1 fragments into the alternate buffer (overlapped with MMAs)
            if (ks < 3) {
                const uint32_t bks = bb + b_row_b + (ks + 1) * 16 * 256;
#pragma unroll
                for (int ni2 = 0; ni2 < 4; ni2++) {
                    uint32_t t[4];
                    ldsm_x4_t(t, bks + b_chk[ni2]);
                    bf[nxt][ni2 * 2][0] = t[0]; bf[nxt][ni2 * 2][1] = t[1];
                    bf[nxt][ni2 * 2 + 1][0] = t[2]; bf[nxt][ni2 * 2 + 1][1] = t[3];
                }
#pragma unroll
                for (int mi = 0; mi < 4; mi++)
                    ldsm_x4(af[nxt][mi], ab + a_row_b[mi] + a_chk[ks + 1]);
            }
#pragma unroll
            for (int mi = 0; mi < 4; mi++)
#pragma unroll
                for (int ni = 0; ni < 8; ni++)
                    mma_f16(acc[mi][ni], af[cur][mi], bf[cur][ni]);
        }
    }

    // epilogue: bias + optional gelu
    const int g = lane >> 2, t = lane & 3;
    const float* be = bias + (size_t)expert * Ncols + (size_t)bn * BN;

#pragma unroll
    for (int mi = 0; mi < 4; mi++) {
        const int gr0 = bm * BM + wm + mi * 16 + g;
#pragma unroll
        for (int ni = 0; ni < 8; ni++) {
            const int lc = wn + ni * 8 + 2 * t;
            const float bv0 = be[lc];
            const float bv1 = be[lc + 1];
            float v0 = acc[mi][ni][0] + bv0;
            float v1 = acc[mi][ni][1] + bv1;
            float v2 = acc[mi][ni][2] + bv0;
            float v3 = acc[mi][ni][3] + bv1;
            if (GELU) {
                v0 = gelu_tanh(v0); v1 = gelu_tanh(v1);
                v2 = gelu_tanh(v2); v3 = gelu_tanh(v3);
            }
            const size_t base0 = (size_t)gr0 * Ncols + (size_t)bn * BN + lc;
            const size_t base1 = (size_t)(gr0 + 8) * Ncols + (size_t)bn * BN + lc;
            if (OUTH) {
                __half* C = (__half*)Cv;
                *reinterpret_cast<__half2*>(C + base0) = __floats2half2_rn(v0, v1);
                *reinterpret_cast<__half2*>(C + base1) = __floats2half2_rn(v2, v3);
            } else {
                float* C = (float*)Cv;
                *reinterpret_cast<float2*>(C + base0) = make_float2(v0, v1);
                *reinterpret_cast<float2*>(C + base1) = make_float2(v2, v3);
            }
        }
    }
}

// ---------------- prepass: fp32 -> fp16 elementwise ----------------
__global__ void conv_h(const float* __restrict__ in, __half* __restrict__ out) {
    size_t i = ((size_t)blockIdx.x * blockDim.x + threadIdx.x) * 8;
    float4 v0 = *reinterpret_cast<const float4*>(in + i);
    float4 v1 = *reinterpret_cast<const float4*>(in + i + 4);
    __half2* o = reinterpret_cast<__half2*>(out + i);
    o[0] = __floats2half2_rn(v0.x, v0.y);
    o[1] = __floats2half2_rn(v0.z, v0.w);
    o[2] = __floats2half2_rn(v1.x, v1.y);
    o[3] = __floats2half2_rn(v1.z, v1.w);
}

// ---------------- launch ----------------
extern "C" void kernel_launch(void* const* d_in, const int* in_sizes, int n_in,
                              void* d_out, int out_size)
{
    const float* x  = (const float*)d_in[0];
    const float* w1 = (const float*)d_in[1];
    const float* b1 = (const float*)d_in[2];
    const float* w2 = (const float*)d_in[3];
    const float* b2 = (const float*)d_in[4];
    float* out = (float*)d_out;

    void *xh_p, *w1h_p, *w2h_p, *hh_p;
    cudaGetSymbolAddress(&xh_p,  g_xh);
    cudaGetSymbolAddress(&w1h_p, g_w1h);
    cudaGetSymbolAddress(&w2h_p, g_w2h);
    cudaGetSymbolAddress(&hh_p,  g_hh);
    __half* xh  = (__half*)xh_p;
    __half* w1h = (__half*)w1h_p;
    __half* w2h = (__half*)w2h_p;
    __half* hh  = (__half*)hh_p;

    cudaFuncSetAttribute(gemm_hmma<true, true>,
                         cudaFuncAttributeMaxDynamicSharedMemorySize, (int)SMEM_BYTES);
    cudaFuncSetAttribute(gemm_hmma<false, false>,
                         cudaFuncAttributeMaxDynamicSharedMemorySize, (int)SMEM_BYTES);

    // prepass conversions
    conv_h<<<(size_t)MTOT * D_ / (256 * 8), 256>>>(x, xh);
    conv_h<<<(size_t)E_ * D_ * F_ / (256 * 8), 256>>>(w1, w1h);
    conv_h<<<(size_t)E_ * F_ * D_ / (256 * 8), 256>>>(w2, w2h);

    // GEMM1: H = gelu(X @ W1 + b1)   M=32768, K=1024, N=4096 (fp16 out)
    gemm_hmma<true, true><<<dim3(F_ / BN, MTOT / BM), 128, SMEM_BYTES>>>(
        xh, w1h, b1, (void*)hh, D_, F_);
    // GEMM2: OUT = H @ W2 + b2       M=32768, K=4096, N=1024 (fp32 out)
    gemm_hmma<false, false><<<dim3(D_ / BN, MTOT / BM), 128, SMEM_BYTES>>>(
        hh, w2h, b2, (void*)out, F_, D_);
}

// round 10
// speedup vs baseline: 1.1391x; 1.0441x over previous
#include <cuda_runtime.h>
#include <cuda_fp16.h>
#include <math.h>
#include <stdint.h>

// ---------------- problem constants ----------------
#define E_ 8
#define B_ 2
#define N_ 2048
#define D_ 1024
#define F_ 4096
#define MTOT (E_*B_*N_)   // 32768 flat rows
#define RPE  (B_*N_)      // 4096 rows per expert

// ---------------- static scratch (allocation-free rule) ----------------
__device__ __half g_xh [(size_t)MTOT * D_];    //  64 MB : X fp16
__device__ __half g_w1h[(size_t)E_ * D_ * F_]; //  64 MB : W1 fp16 [E][D][F]
__device__ __half g_w2h[(size_t)E_ * F_ * D_]; //  64 MB : W2 fp16 [E][F][D]
__device__ __half g_hh [(size_t)MTOT * F_];    // 256 MB : H fp16

// ---------------- tiling ----------------
// A stage: 128 rows x 128 B (BK=64 halves), XOR-swizzled 16B chunks
// B stage: 64 rows x 256 B (BN=128 halves), XOR-swizzled 16B chunks
constexpr int BM = 128, BN = 128, BK = 64;
constexpr int NSTAGE = 3;
constexpr int ASTAGE_B = BM * 128;             // 16384 B
constexpr int BSTAGE_B = BK * 256;             // 16384 B
constexpr int STAGE_B  = ASTAGE_B + BSTAGE_B;  // 32768 B
constexpr size_t SMEM_BYTES = (size_t)NSTAGE * STAGE_B; // 98304 B

// ---------------- helpers ----------------
__device__ __forceinline__ uint32_t s2u(const void* p) {
    uint32_t a;
    asm("{ .reg .u64 t; cvta.to.shared.u64 t, %1; cvt.u32.u64 %0, t; }" : "=r"(a) : "l"(p));
    return a;
}
__device__ __forceinline__ void cpa16(uint32_t s, const void* g) {
    asm volatile("cp.async.cg.shared.global [%0], [%1], 16;" :: "r"(s), "l"(g));
}
__device__ __forceinline__ void commitg() {
    asm volatile("cp.async.commit_group;" ::: "memory");
}
__device__ __forceinline__ void ldsm_x4(uint32_t* r, uint32_t a) {
    asm volatile("ldmatrix.sync.aligned.m8n8.x4.shared.b16 {%0,%1,%2,%3}, [%4];"
                 : "=r"(r[0]), "=r"(r[1]), "=r"(r[2]), "=r"(r[3]) : "r"(a));
}
__device__ __forceinline__ void ldsm_x4_t(uint32_t* r, uint32_t a) {
    asm volatile("ldmatrix.sync.aligned.m8n8.x4.trans.shared.b16 {%0,%1,%2,%3}, [%4];"
                 : "=r"(r[0]), "=r"(r[1]), "=r"(r[2]), "=r"(r[3]) : "r"(a));
}
__device__ __forceinline__ void mma_f16(float* c, const uint32_t* a, const uint32_t* b) {
    asm volatile(
        "mma.sync.aligned.m16n8k16.row.col.f32.f16.f16.f32 "
        "{%0,%1,%2,%3},{%4,%5,%6,%7},{%8,%9},{%0,%1,%2,%3};"
        : "+f"(c[0]), "+f"(c[1]), "+f"(c[2]), "+f"(c[3])
        : "r"(a[0]), "r"(a[1]), "r"(a[2]), "r"(a[3]), "r"(b[0]), "r"(b[1]));
}

// jax.nn.gelu default (tanh form), via exact identity:
// 0.5*x*(1+tanh(u)) == x * sigmoid(2u) == x / (1 + e^{-2u})
// Saturation-safe: u->+inf => e^{-2u}=0 => x ; u->-inf => e^{-2u}=inf => x/inf = 0.
__device__ __forceinline__ float gelu_tanh(float x) {
    float u = 0.7978845608028654f * fmaf(0.044715f * x, x * x, x);
    float s = __expf(-2.0f * u);
    return __fdividef(x, 1.0f + s);
}

// ---------------- stage loader (128 threads) ----------------
__device__ __forceinline__ void load_stage(uint32_t sbase, const __half* Ae, const __half* Be,
                                           int K, int Ncols, int kt, int tid) {
    const uint32_t ab = sbase + (kt % NSTAGE) * STAGE_B;
    const uint32_t bb = ab + ASTAGE_B;
    const char* ag = (const char*)(Ae + (size_t)kt * BK);
    const char* bg = (const char*)(Be + (size_t)kt * BK * Ncols);
    // A: 128 rows x 8 chunks = 1024 chunks ; 8 per thread
#pragma unroll
    for (int i = 0; i < 8; i++) {
        int c = tid + i * 128;
        int r = c >> 3, cb = c & 7;
        cpa16(ab + r * 128 + ((cb ^ (r & 7)) << 4), ag + (size_t)r * K * 2 + cb * 16);
    }
    // B: 64 rows x 16 chunks = 1024 chunks ; 8 per thread
#pragma unroll
    for (int i = 0; i < 8; i++) {
        int c = tid + i * 128;
        int r = c >> 4, cb = c & 15;
        cpa16(bb + r * 256 + ((cb ^ (r & 7)) << 4), bg + (size_t)r * Ncols * 2 + cb * 16);
    }
    commitg();
}

// ---------------- GEMM: C = act(A @ W_e + bias_e) ----------------
// A:[MTOT,K] fp16 rm; W:[E][K][Ncols] fp16 rm; bias:[E][Ncols] fp32
// block = 128 threads = 4 warps, warp tile 64x64
template <bool GELU, bool OUTH>
__global__ void __launch_bounds__(128, 2)
gemm_hmma(const __half* __restrict__ A, const __half* __restrict__ W,
          const float* __restrict__ bias, void* __restrict__ Cv, int K, int Ncols)
{
    extern __shared__ char smem[];
    const uint32_t sb = s2u(smem);
    const int tid = threadIdx.x;
    const int warp = tid >> 5, lane = tid & 31;
    const int bm = blockIdx.y, bn = blockIdx.x;
    const int expert = (bm * BM) / RPE;

    const __half* Ae = A + (size_t)bm * BM * K;
    const __half* Be = W + (size_t)expert * K * Ncols + (size_t)bn * BN;

    const int wm = (warp & 1) * 64;   // 2 warps along M
    const int wn = (warp >> 1) * 64;  // 2 warps along N

    float acc[4][8][4];
#pragma unroll
    for (int mi = 0; mi < 4; mi++)
#pragma unroll
        for (int ni = 0; ni < 8; ni++)
#pragma unroll
            for (int r = 0; r < 4; r++) acc[mi][ni][r] = 0.0f;

    const int KT = K / BK;
    const int l16 = lane & 15, lh = lane >> 4;
    const int rxor = l16 & 7;         // row&7 == l16&7 for all fragment rows

    // hoisted swizzled offsets
    uint32_t a_row_b[4];
#pragma unroll
    for (int mi = 0; mi < 4; mi++)
        a_row_b[mi] = (wm + mi * 16 + l16) * 128;
    uint32_t a_chk[4];
#pragma unroll
    for (int ks = 0; ks < 4; ks++)
        a_chk[ks] = (uint32_t)(((ks * 2 + lh) ^ rxor) << 4);
    const uint32_t b_row_b = l16 * 256;
    uint32_t b_chk[4];
#pragma unroll
    for (int ni2 = 0; ni2 < 4; ni2++)
        b_chk[ni2] = (uint32_t)((((wn >> 3) + ni2 * 2 + lh) ^ rxor) << 4);

    // prologue: 2 stages in flight
    load_stage(sb, Ae, Be, K, Ncols, 0, tid);
    load_stage(sb, Ae, Be, K, Ncols, 1, tid);

    for (int kt = 0; kt < KT; kt++) {
        // wait only the oldest outstanding group (stage kt); stage kt+1 may still fly
        if (kt + 1 < KT) asm volatile("cp.async.wait_group 1;" ::: "memory");
        else             asm volatile("cp.async.wait_group 0;" ::: "memory");
        __syncthreads();

        if (kt + 2 < KT) load_stage(sb, Ae, Be, K, Ncols, kt + 2, tid);

        const uint32_t ab = sb + (kt % NSTAGE) * STAGE_B;
        const uint32_t bb = ab + ASTAGE_B;

#pragma unroll
        for (int ks = 0; ks < 4; ks++) {
            // B fragments first
            uint32_t bf[8][2];
            const uint32_t bks = bb + b_row_b + ks * 16 * 256;
#pragma unroll
            for (int ni2 = 0; ni2 < 4; ni2++) {
                uint32_t t[4];
                ldsm_x4_t(t, bks + b_chk[ni2]);
                bf[ni2 * 2][0] = t[0]; bf[ni2 * 2][1] = t[1];
                bf[ni2 * 2 + 1][0] = t[2]; bf[ni2 * 2 + 1][1] = t[3];
            }
            // interleave A loads with MMA blocks: load af[mi+1] while mma(mi) runs
            uint32_t af[4][4];
            ldsm_x4(af[0], ab + a_row_b[0] + a_chk[ks]);
#pragma unroll
            for (int mi = 0; mi < 4; mi++) {
                if (mi < 3)
                    ldsm_x4(af[mi + 1], ab + a_row_b[mi + 1] + a_chk[ks]);
#pragma unroll
                for (int ni = 0; ni < 8; ni++)
                    mma_f16(acc[mi][ni], af[mi], bf[ni]);
            }
        }
    }

    // epilogue: bias + optional gelu
    const int g = lane >> 2, t = lane & 3;
    const float* be = bias + (size_t)expert * Ncols + (size_t)bn * BN;

#pragma unroll
    for (int mi = 0; mi < 4; mi++) {
        const int gr0 = bm * BM + wm + mi * 16 + g;
#pragma unroll
        for (int ni = 0; ni < 8; ni++) {
            const int lc = wn + ni * 8 + 2 * t;
            const float bv0 = be[lc];
            const float bv1 = be[lc + 1];
            float v0 = acc[mi][ni][0] + bv0;
            float v1 = acc[mi][ni][1] + bv1;
            float v2 = acc[mi][ni][2] + bv0;
            float v3 = acc[mi][ni][3] + bv1;
            if (GELU) {
                v0 = gelu_tanh(v0); v1 = gelu_tanh(v1);
                v2 = gelu_tanh(v2); v3 = gelu_tanh(v3);
            }
            const size_t base0 = (size_t)gr0 * Ncols + (size_t)bn * BN + lc;
            const size_t base1 = (size_t)(gr0 + 8) * Ncols + (size_t)bn * BN + lc;
            if (OUTH) {
                __half* C = (__half*)Cv;
                *reinterpret_cast<__half2*>(C + base0) = __floats2half2_rn(v0, v1);
                *reinterpret_cast<__half2*>(C + base1) = __floats2half2_rn(v2, v3);
            } else {
                float* C = (float*)Cv;
                *reinterpret_cast<float2*>(C + base0) = make_float2(v0, v1);
                *reinterpret_cast<float2*>(C + base1) = make_float2(v2, v3);
            }
        }
    }
}

// ---------------- merged prepass: X, W1, W2 -> fp16 (all exactly 33,554,432 elems) ----------------
__global__ void conv_all(const float* __restrict__ x,  __half* __restrict__ xh,
                         const float* __restrict__ w1, __half* __restrict__ w1h,
                         const float* __restrict__ w2, __half* __restrict__ w2h)
{
    size_t i = ((size_t)blockIdx.x * blockDim.x + threadIdx.x) * 8;
#pragma unroll
    for (int s = 0; s < 3; s++) {
        const float* in  = (s == 0) ? x  : (s == 1) ? w1  : w2;
        __half*      out = (s == 0) ? xh : (s == 1) ? w1h : w2h;
        float4 v0 = *reinterpret_cast<const float4*>(in + i);
        float4 v1 = *reinterpret_cast<const float4*>(in + i + 4);
        __half2* o = reinterpret_cast<__half2*>(out + i);
        o[0] = __floats2half2_rn(v0.x, v0.y);
        o[1] = __floats2half2_rn(v0.z, v0.w);
        o[2] = __floats2half2_rn(v1.x, v1.y);
        o[3] = __floats2half2_rn(v1.z, v1.w);
    }
}

// ---------------- launch ----------------
extern "C" void kernel_launch(void* const* d_in, const int* in_sizes, int n_in,
                              void* d_out, int out_size)
{
    const float* x  = (const float*)d_in[0];
    const float* w1 = (const float*)d_in[1];
    const float* b1 = (const float*)d_in[2];
    const float* w2 = (const float*)d_in[3];
    const float* b2 = (const float*)d_in[4];
    float* out = (float*)d_out;

    void *xh_p, *w1h_p, *w2h_p, *hh_p;
    cudaGetSymbolAddress(&xh_p,  g_xh);
    cudaGetSymbolAddress(&w1h_p, g_w1h);
    cudaGetSymbolAddress(&w2h_p, g_w2h);
    cudaGetSymbolAddress(&hh_p,  g_hh);
    __half* xh  = (__half*)xh_p;
    __half* w1h = (__half*)w1h_p;
    __half* w2h = (__half*)w2h_p;
    __half* hh  = (__half*)hh_p;

    cudaFuncSetAttribute(gemm_hmma<true, true>,
                         cudaFuncAttributeMaxDynamicSharedMemorySize, (int)SMEM_BYTES);
    cudaFuncSetAttribute(gemm_hmma<false, false>,
                         cudaFuncAttributeMaxDynamicSharedMemorySize, (int)SMEM_BYTES);

    // merged prepass: all three tensors are 33,554,432 elements
    conv_all<<<(size_t)MTOT * D_ / (256 * 8), 256>>>(x, xh, w1, w1h, w2, w2h);

    // GEMM1: H = gelu(X @ W1 + b1)   M=32768, K=1024, N=4096 (fp16 out)
    gemm_hmma<true, true><<<dim3(F_ / BN, MTOT / BM), 128, SMEM_BYTES>>>(
        xh, w1h, b1, (void*)hh, D_, F_);
    // GEMM2: OUT = H @ W2 + b2       M=32768, K=4096, N=1024 (fp32 out)
    gemm_hmma<false, false><<<dim3(D_ / BN, MTOT / BM), 128, SMEM_BYTES>>>(
        hh, w2h, b2, (void*)out, F_, D_);
}